// round 1
// baseline (speedup 1.0000x reference)
#include <cuda_runtime.h>

// Problem constants (B=1, N=4, C=16, D=64, H=128, W=128)
#define NCTX 4
#define CH   16
#define VOX  (64 * 128 * 128)   // 1,048,576 voxels
#define VPT  4                  // voxels per thread (float4)
#define TPB  256

__global__ __launch_bounds__(TPB) void volattn3d_kernel(
    const float* __restrict__ q,      // [C][V]
    const float* __restrict__ k,      // [N][C][V]
    const float* __restrict__ v,      // [N][C][V]
    const float* __restrict__ w_proj, // [C][C]  (row o, col c)
    const float* __restrict__ b_proj, // [C]
    float* __restrict__ out)          // [C][V]
{
    __shared__ float sw[CH * CH];
    __shared__ float sb[CH];
    {
        int t = threadIdx.x;
        if (t < CH * CH) sw[t] = w_proj[t];
        if (t < CH)      sb[t] = b_proj[t];
    }
    __syncthreads();

    const int p = (blockIdx.x * TPB + threadIdx.x) * VPT;   // base voxel

    // ---- load q[c] for this voxel quad ----
    float4 qv[CH];
#pragma unroll
    for (int c = 0; c < CH; ++c)
        qv[c] = *reinterpret_cast<const float4*>(q + c * VOX + p);

    // ---- scores[n] = (q . k_n) / 4 ----
    float4 sc[NCTX];
#pragma unroll
    for (int n = 0; n < NCTX; ++n) {
        float4 s = make_float4(0.f, 0.f, 0.f, 0.f);
#pragma unroll
        for (int c = 0; c < CH; ++c) {
            float4 kv = *reinterpret_cast<const float4*>(k + (n * CH + c) * VOX + p);
            s.x = fmaf(qv[c].x, kv.x, s.x);
            s.y = fmaf(qv[c].y, kv.y, s.y);
            s.z = fmaf(qv[c].z, kv.z, s.z);
            s.w = fmaf(qv[c].w, kv.w, s.w);
        }
        const float inv_sqrt_c = 0.25f;  // 1/sqrt(16)
        sc[n] = make_float4(s.x * inv_sqrt_c, s.y * inv_sqrt_c,
                            s.z * inv_sqrt_c, s.w * inv_sqrt_c);
    }

    // ---- softmax over n (per lane component) ----
    float4 mx = sc[0];
#pragma unroll
    for (int n = 1; n < NCTX; ++n) {
        mx.x = fmaxf(mx.x, sc[n].x);
        mx.y = fmaxf(mx.y, sc[n].y);
        mx.z = fmaxf(mx.z, sc[n].z);
        mx.w = fmaxf(mx.w, sc[n].w);
    }
    float4 ssum = make_float4(0.f, 0.f, 0.f, 0.f);
#pragma unroll
    for (int n = 0; n < NCTX; ++n) {
        sc[n].x = __expf(sc[n].x - mx.x);
        sc[n].y = __expf(sc[n].y - mx.y);
        sc[n].z = __expf(sc[n].z - mx.z);
        sc[n].w = __expf(sc[n].w - mx.w);
        ssum.x += sc[n].x; ssum.y += sc[n].y;
        ssum.z += sc[n].z; ssum.w += sc[n].w;
    }
    const float4 rs = make_float4(__frcp_rn(ssum.x), __frcp_rn(ssum.y),
                                  __frcp_rn(ssum.z), __frcp_rn(ssum.w));
#pragma unroll
    for (int n = 0; n < NCTX; ++n) {
        sc[n].x *= rs.x; sc[n].y *= rs.y;
        sc[n].z *= rs.z; sc[n].w *= rs.w;
    }

    // ---- x[c] = sum_n attn[n] * v[n][c] ----
    float4 x[CH];
#pragma unroll
    for (int c = 0; c < CH; ++c) x[c] = make_float4(0.f, 0.f, 0.f, 0.f);
#pragma unroll
    for (int n = 0; n < NCTX; ++n) {
#pragma unroll
        for (int c = 0; c < CH; ++c) {
            float4 vv = *reinterpret_cast<const float4*>(v + (n * CH + c) * VOX + p);
            x[c].x = fmaf(sc[n].x, vv.x, x[c].x);
            x[c].y = fmaf(sc[n].y, vv.y, x[c].y);
            x[c].z = fmaf(sc[n].z, vv.z, x[c].z);
            x[c].w = fmaf(sc[n].w, vv.w, x[c].w);
        }
    }

    // ---- out[o] = sum_c w[o][c] * x[c] + b[o] ----
#pragma unroll
    for (int o = 0; o < CH; ++o) {
        const float bo = sb[o];
        float4 acc = make_float4(bo, bo, bo, bo);
#pragma unroll
        for (int c = 0; c < CH; ++c) {
            const float wv = sw[o * CH + c];
            acc.x = fmaf(wv, x[c].x, acc.x);
            acc.y = fmaf(wv, x[c].y, acc.y);
            acc.z = fmaf(wv, x[c].z, acc.z);
            acc.w = fmaf(wv, x[c].w, acc.w);
        }
        *reinterpret_cast<float4*>(out + o * VOX + p) = acc;
    }
}

extern "C" void kernel_launch(void* const* d_in, const int* in_sizes, int n_in,
                              void* d_out, int out_size) {
    const float* q      = (const float*)d_in[0];
    const float* k      = (const float*)d_in[1];
    const float* v      = (const float*)d_in[2];
    const float* w_proj = (const float*)d_in[3];
    const float* b_proj = (const float*)d_in[4];
    float* out = (float*)d_out;

    const int threads = VOX / VPT;            // 262,144
    const int grid = threads / TPB;           // 1024
    volattn3d_kernel<<<grid, TPB>>>(q, k, v, w_proj, b_proj, out);
}

// round 2
// speedup vs baseline: 1.1310x; 1.1310x over previous
#include <cuda_runtime.h>

// Problem constants (B=1, N=4, C=16, D=64, H=128, W=128)
#define NCTX 4
#define CH   16
#define VOX  (64 * 128 * 128)   // 1,048,576 voxels
#define VPT  2                  // voxels per thread (float2)
#define TPB  256

__global__ __launch_bounds__(TPB, 4) void volattn3d_kernel(
    const float* __restrict__ q,      // [C][V]
    const float* __restrict__ k,      // [N][C][V]
    const float* __restrict__ v,      // [N][C][V]
    const float* __restrict__ w_proj, // [C][C]
    const float* __restrict__ b_proj, // [C]
    float* __restrict__ out)          // [C][V]
{
    __shared__ float sw[CH * CH];
    __shared__ float sb[CH];
    {
        int t = threadIdx.x;
        if (t < CH * CH) sw[t] = w_proj[t];
        if (t < CH)      sb[t] = b_proj[t];
    }
    __syncthreads();

    const int p = (blockIdx.x * TPB + threadIdx.x) * VPT;   // base voxel pair

    // ---- scores[n] = (q . k_n), c-outer so q is never array-resident ----
    float2 sc[NCTX];
#pragma unroll
    for (int n = 0; n < NCTX; ++n) sc[n] = make_float2(0.f, 0.f);

#pragma unroll
    for (int c = 0; c < CH; ++c) {
        const float2 qv = __ldcs(reinterpret_cast<const float2*>(q + c * VOX + p));
#pragma unroll
        for (int n = 0; n < NCTX; ++n) {
            const float2 kv = __ldcs(reinterpret_cast<const float2*>(k + (n * CH + c) * VOX + p));
            sc[n].x = fmaf(qv.x, kv.x, sc[n].x);
            sc[n].y = fmaf(qv.y, kv.y, sc[n].y);
        }
    }
    // scale by 1/sqrt(C) = 0.25
#pragma unroll
    for (int n = 0; n < NCTX; ++n) { sc[n].x *= 0.25f; sc[n].y *= 0.25f; }

    // ---- softmax over n ----
    float2 mx = sc[0];
#pragma unroll
    for (int n = 1; n < NCTX; ++n) {
        mx.x = fmaxf(mx.x, sc[n].x);
        mx.y = fmaxf(mx.y, sc[n].y);
    }
    float2 ssum = make_float2(0.f, 0.f);
#pragma unroll
    for (int n = 0; n < NCTX; ++n) {
        sc[n].x = __expf(sc[n].x - mx.x);
        sc[n].y = __expf(sc[n].y - mx.y);
        ssum.x += sc[n].x;
        ssum.y += sc[n].y;
    }
    const float2 rs = make_float2(__frcp_rn(ssum.x), __frcp_rn(ssum.y));
#pragma unroll
    for (int n = 0; n < NCTX; ++n) { sc[n].x *= rs.x; sc[n].y *= rs.y; }

    // ---- x[c] = sum_n attn[n] * v[n][c] ----
    float2 x[CH];
#pragma unroll
    for (int c = 0; c < CH; ++c) x[c] = make_float2(0.f, 0.f);
#pragma unroll
    for (int n = 0; n < NCTX; ++n) {
#pragma unroll
        for (int c = 0; c < CH; ++c) {
            const float2 vv = __ldcs(reinterpret_cast<const float2*>(v + (n * CH + c) * VOX + p));
            x[c].x = fmaf(sc[n].x, vv.x, x[c].x);
            x[c].y = fmaf(sc[n].y, vv.y, x[c].y);
        }
    }

    // ---- out[o] = sum_c w[o][c] * x[c] + b[o] ----
#pragma unroll
    for (int o = 0; o < CH; ++o) {
        const float bo = sb[o];
        float2 acc = make_float2(bo, bo);
#pragma unroll
        for (int c = 0; c < CH; ++c) {
            const float wv = sw[o * CH + c];
            acc.x = fmaf(wv, x[c].x, acc.x);
            acc.y = fmaf(wv, x[c].y, acc.y);
        }
        __stcs(reinterpret_cast<float2*>(out + o * VOX + p), acc);
    }
}

extern "C" void kernel_launch(void* const* d_in, const int* in_sizes, int n_in,
                              void* d_out, int out_size) {
    const float* q      = (const float*)d_in[0];
    const float* k      = (const float*)d_in[1];
    const float* v      = (const float*)d_in[2];
    const float* w_proj = (const float*)d_in[3];
    const float* b_proj = (const float*)d_in[4];
    float* out = (float*)d_out;

    const int threads = VOX / VPT;            // 524,288
    const int grid = threads / TPB;           // 2048
    volattn3d_kernel<<<grid, TPB>>>(q, k, v, w_proj, b_proj, out);
}